// round 1
// baseline (speedup 1.0000x reference)
#include <cuda_runtime.h>
#include <cstdint>

#define N_NODES 50000
#define DD 128
#define RR 8

#define BM 128
#define BN 128
#define BK 32
#define ASTR (BK + 4)   // 36 floats: bank step 4 -> conflict-free A frag loads
#define BSTR (BN + 8)   // 136 floats: bank step 8 -> conflict-free B frag loads

// ---- scratch (static device globals; no runtime allocation) ----
__device__ float g_z[(size_t)N_NODES * RR * DD];   // 204.8 MB: z[n][r][e]
__device__ float g_h[(size_t)N_NODES * DD];        // 25.6 MB: hidden layer
__device__ float g_inv[N_NODES * RR];              // 1/max(cnt,1)
__device__ int   g_cnt[N_NODES * RR];
__device__ int   g_flags[2];                       // [0]: edge_index is int64, [1]: edge_type is int64

// ---------------------------------------------------------------
// dtype detection: int64 little-endian with values < 2^31 has all
// odd 32-bit words == 0. int32 random node/relation ids make the
// all-zero pattern impossible in practice.
__global__ void detect_kernel(const unsigned* __restrict__ ei,
                              const unsigned* __restrict__ et) {
    if (threadIdx.x == 0 && blockIdx.x == 0) {
        unsigned a = 0, b = 0;
        for (int j = 1; j < 64; j += 2) { a |= ei[j]; b |= et[j]; }
        g_flags[0] = (a == 0) ? 1 : 0;
        g_flags[1] = (b == 0) ? 1 : 0;
    }
}

__device__ __forceinline__ long long ld_idx(const void* p, long long i, int is64) {
    return is64 ? ((const long long*)p)[i] : (long long)((const int*)p)[i];
}

__global__ void zero_cnt_kernel(int n) {
    int i = blockIdx.x * blockDim.x + threadIdx.x;
    if (i < n) g_cnt[i] = 0;
}

__global__ void count_kernel(const void* __restrict__ ei,
                             const void* __restrict__ et, int E) {
    int e = blockIdx.x * blockDim.x + threadIdx.x;
    if (e >= E) return;
    int is64i = g_flags[0], is64t = g_flags[1];
    int dst = (int)ld_idx(ei, (long long)E + e, is64i);
    int rel = (int)ld_idx(et, e, is64t);
    atomicAdd(&g_cnt[dst * RR + rel], 1);
}

__global__ void inv_kernel(int n) {
    int i = blockIdx.x * blockDim.x + threadIdx.x;
    if (i < n) {
        int c = g_cnt[i];
        g_inv[i] = 1.0f / (float)(c > 0 ? c : 1);
    }
}

// ---------------------------------------------------------------
__device__ __forceinline__ float to_tf32(float x) {
    float r;
    asm("cvt.rna.tf32.f32 %0, %1;" : "=f"(r) : "f"(x));
    return r;
}

__device__ __forceinline__ void mma_tf32(float* c, const unsigned* a, const unsigned* b) {
    asm volatile(
        "mma.sync.aligned.m16n8k8.row.col.f32.tf32.tf32.f32 "
        "{%0,%1,%2,%3}, {%4,%5,%6,%7}, {%8,%9}, {%0,%1,%2,%3};"
        : "+f"(c[0]), "+f"(c[1]), "+f"(c[2]), "+f"(c[3])
        : "r"(a[0]), "r"(a[1]), "r"(a[2]), "r"(a[3]), "r"(b[0]), "r"(b[1]));
}

// C[n0:n0+128, block bz]:  bz<8 -> z[n][bz][:] = A[n,:] @ w[bz]
//                          bz==8 -> out[n][:] = A[n,:] @ root + bias
__global__ __launch_bounds__(256)
void gemm_kernel(const float* __restrict__ Aopt,
                 const float* __restrict__ W,
                 const float* __restrict__ root,
                 const float* __restrict__ bias,
                 float* __restrict__ dout, int nrows) {
    __shared__ float As[BM * ASTR];
    __shared__ float Bs[BK * BSTR];

    const float* A = Aopt ? Aopt : g_h;
    int bz = blockIdx.y;
    int n0 = blockIdx.x * BM;
    const float* Bsrc = (bz < RR) ? (W + (size_t)bz * DD * DD) : root;

    int tid = threadIdx.x;
    int lane = tid & 31, wid = tid >> 5;
    int wm = wid & 1, wn = wid >> 1;   // 2 x 4 warps -> 64x32 warp tiles

    float acc[4][4][4];
#pragma unroll
    for (int i = 0; i < 4; i++)
#pragma unroll
        for (int j = 0; j < 4; j++)
#pragma unroll
            for (int k = 0; k < 4; k++) acc[i][j][k] = 0.f;

    const unsigned* As32 = (const unsigned*)As;
    const unsigned* Bs32 = (const unsigned*)Bs;

    for (int k0 = 0; k0 < DD; k0 += BK) {
        // A chunk: 128 x 32, as 1024 float4
#pragma unroll
        for (int it = 0; it < 4; ++it) {
            int i = tid + it * 256;
            int row = i >> 3, quad = i & 7;
            float4 v = make_float4(0.f, 0.f, 0.f, 0.f);
            int gr = n0 + row;
            if (gr < nrows) v = *(const float4*)(A + (size_t)gr * DD + k0 + quad * 4);
            int base = row * ASTR + quad * 4;
            As[base + 0] = to_tf32(v.x);
            As[base + 1] = to_tf32(v.y);
            As[base + 2] = to_tf32(v.z);
            As[base + 3] = to_tf32(v.w);
        }
        // B chunk: 32 x 128, as 1024 float4
#pragma unroll
        for (int it = 0; it < 4; ++it) {
            int i = tid + it * 256;
            int krow = i >> 5, quad = i & 31;
            float4 v = *(const float4*)(Bsrc + (size_t)(k0 + krow) * DD + quad * 4);
            int base = krow * BSTR + quad * 4;
            Bs[base + 0] = to_tf32(v.x);
            Bs[base + 1] = to_tf32(v.y);
            Bs[base + 2] = to_tf32(v.z);
            Bs[base + 3] = to_tf32(v.w);
        }
        __syncthreads();

#pragma unroll
        for (int kk = 0; kk < BK; kk += 8) {
            unsigned afrag[4][4], bfrag[4][2];
#pragma unroll
            for (int mf = 0; mf < 4; mf++) {
                int r0 = wm * 64 + mf * 16 + (lane >> 2);
                int c0 = kk + (lane & 3);
                afrag[mf][0] = As32[r0 * ASTR + c0];
                afrag[mf][1] = As32[(r0 + 8) * ASTR + c0];
                afrag[mf][2] = As32[r0 * ASTR + c0 + 4];
                afrag[mf][3] = As32[(r0 + 8) * ASTR + c0 + 4];
            }
#pragma unroll
            for (int nf = 0; nf < 4; nf++) {
                int nb = wn * 32 + nf * 8 + (lane >> 2);
                bfrag[nf][0] = Bs32[(kk + (lane & 3)) * BSTR + nb];
                bfrag[nf][1] = Bs32[(kk + 4 + (lane & 3)) * BSTR + nb];
            }
#pragma unroll
            for (int mf = 0; mf < 4; mf++)
#pragma unroll
                for (int nf = 0; nf < 4; nf++)
                    mma_tf32(acc[mf][nf], afrag[mf], bfrag[nf]);
        }
        __syncthreads();
    }

    // store
#pragma unroll
    for (int mf = 0; mf < 4; mf++) {
        int r0 = wm * 64 + mf * 16 + (lane >> 2);
#pragma unroll
        for (int nf = 0; nf < 4; nf++) {
            int col = wn * 32 + nf * 8 + 2 * (lane & 3);
#pragma unroll
            for (int h = 0; h < 2; h++) {
                int gr = n0 + r0 + h * 8;
                if (gr < nrows) {
                    float v0 = acc[mf][nf][h * 2 + 0];
                    float v1 = acc[mf][nf][h * 2 + 1];
                    if (bz < RR) {
                        float2* p = (float2*)(g_z + (size_t)gr * (RR * DD) + bz * DD + col);
                        *p = make_float2(v0, v1);
                    } else {
                        float* o = dout ? dout : g_h;
                        float2* p = (float2*)(o + (size_t)gr * DD + col);
                        *p = make_float2(v0 + bias[col], v1 + bias[col + 1]);
                    }
                }
            }
        }
    }
}

// ---------------------------------------------------------------
// one warp per edge: out[dst] += z[src, rel] * inv_cnt[dst, rel]
__global__ void edge_agg_kernel(const void* __restrict__ ei,
                                const void* __restrict__ et,
                                int E, float* __restrict__ dout) {
    int gw = (blockIdx.x * blockDim.x + threadIdx.x) >> 5;
    int lane = threadIdx.x & 31;
    if (gw >= E) return;
    float* out = dout ? dout : g_h;
    int is64i = g_flags[0], is64t = g_flags[1];
    long long src, dst;
    if (is64i) {
        const long long* p = (const long long*)ei;
        src = p[gw]; dst = p[(long long)E + gw];
    } else {
        const int* p = (const int*)ei;
        src = p[gw]; dst = p[E + gw];
    }
    int rel = (int)(is64t ? ((const long long*)et)[gw] : (long long)((const int*)et)[gw]);

    float s = g_inv[(int)dst * RR + rel];
    const float4 v = *(const float4*)(g_z + ((size_t)src * RR + rel) * DD + lane * 4);
    float* dp = out + (size_t)dst * DD + lane * 4;
    asm volatile("red.global.add.v4.f32 [%0], {%1,%2,%3,%4};"
                 :: "l"(dp), "f"(v.x * s), "f"(v.y * s), "f"(v.z * s), "f"(v.w * s)
                 : "memory");
}

__global__ void relu_kernel(float* __restrict__ dout, int n4) {
    int i = blockIdx.x * blockDim.x + threadIdx.x;
    if (i >= n4) return;
    float* p = dout ? dout : g_h;
    float4 v = ((float4*)p)[i];
    v.x = fmaxf(v.x, 0.f); v.y = fmaxf(v.y, 0.f);
    v.z = fmaxf(v.z, 0.f); v.w = fmaxf(v.w, 0.f);
    ((float4*)p)[i] = v;
}

// ---------------------------------------------------------------
extern "C" void kernel_launch(void* const* d_in, const int* in_sizes, int n_in,
                              void* d_out, int out_size) {
    const float* x     = (const float*)d_in[0];
    const void*  ei    = d_in[1];
    const void*  et    = d_in[2];
    const float* w1    = (const float*)d_in[3];
    const float* root1 = (const float*)d_in[4];
    const float* b1    = (const float*)d_in[5];
    const float* w2    = (const float*)d_in[6];
    const float* root2 = (const float*)d_in[7];
    const float* b2    = (const float*)d_in[8];
    float* out = (float*)d_out;

    int E = in_sizes[2];            // edge_type element count
    int N = in_sizes[0] / DD;       // 50000

    detect_kernel<<<1, 32>>>((const unsigned*)ei, (const unsigned*)et);

    int nr = N * RR;
    zero_cnt_kernel<<<(nr + 255) / 256, 256>>>(nr);
    count_kernel<<<(E + 255) / 256, 256>>>(ei, et, E);
    inv_kernel<<<(nr + 255) / 256, 256>>>(nr);

    dim3 gg((N + BM - 1) / BM, RR + 1);
    int edge_blocks = (E * 32 + 255) / 256;
    int relu_n4 = N * DD / 4;

    // layer 1: x -> g_h
    gemm_kernel<<<gg, 256>>>(x, w1, root1, b1, nullptr, N);
    edge_agg_kernel<<<edge_blocks, 256>>>(ei, et, E, nullptr);
    relu_kernel<<<(relu_n4 + 255) / 256, 256>>>(nullptr, relu_n4);

    // layer 2: g_h -> out
    gemm_kernel<<<gg, 256>>>(nullptr, w2, root2, b2, out, N);
    edge_agg_kernel<<<edge_blocks, 256>>>(ei, et, E, out);
    relu_kernel<<<(relu_n4 + 255) / 256, 256>>>(out, relu_n4);
}